// round 7
// baseline (speedup 1.0000x reference)
#include <cuda_runtime.h>
#include <cuda_bf16.h>
#include <cstdint>

// ============================================================================
// S = 256 states/vocab, B = 16 sequences, L = 512 tokens.
// sparsemax_loss_vec(z)[y] = C(z) - z[y], C(z) = tau + 0.5*sum(p^2) + 0.5
// Backward recurrence (log semiring):
//   c_t[q] = G[x][q] + log( sum_n exp(-T[q,x,n]) * exp(c_{t+1}[n] - cmax) ) + cmax
//   G[x][q] = cE[q] - E[q,x] + cT[q,x]
// out = sum_b LSE_q( (cA - alpha[q]) + c_0[b,q] ),  c_L[q] = cOmega - omega[q]
//
// k_forward: 8 clusters x 8 CTAs; each cluster interleaves TWO batches so the
// cluster-scope sync latency of one batch hides under the other's compute.
// ============================================================================

#define SS 256
#define BB 16
#define LL 512
#define CLUSTER 8

// -------- device scratch --------
__device__ float          g_cT[SS * SS];
__device__ float          g_cE[SS];
__device__ float          g_Gtab[SS * SS];            // [x][q]
__device__ float          g_c0[SS];
__device__ float          g_LAl[SS];
__device__ __nv_bfloat16  g_M[(size_t)SS * SS * SS];  // [x][next][q] = exp(-T[q,x,next])
__device__ float          g_perseq[BB];

// -------- helpers --------
__device__ __forceinline__ float wredMax(float v) {
#pragma unroll
    for (int o = 16; o; o >>= 1) v = fmaxf(v, __shfl_xor_sync(0xffffffffu, v, o));
    return v;
}
__device__ __forceinline__ float wredSum(float v) {
#pragma unroll
    for (int o = 16; o; o >>= 1) v += __shfl_xor_sync(0xffffffffu, v, o);
    return v;
}

// MUFU-free exp (|x| <= ~0.8 here)
__device__ __forceinline__ float exp_poly(float x) {
    float y = x * 1.44269504088896341f;
    float n = rintf(y);
    float t = (y - n) * 0.6931471805599453f;
    float p = 1.98412698412698413e-4f;
    p = fmaf(p, t, 1.38888888888888889e-3f);
    p = fmaf(p, t, 8.33333333333333333e-3f);
    p = fmaf(p, t, 4.16666666666666667e-2f);
    p = fmaf(p, t, 1.66666666666666667e-1f);
    p = fmaf(p, t, 0.5f);
    p = fmaf(p, t, 1.0f);
    p = fmaf(p, t, 1.0f);
    return p * __int_as_float(((int)n + 127) << 23);
}

// C(z) via Newton on f(tau) = sum relu(z - tau) - 1 (convex, piecewise linear,
// decreasing). Start tau0 = zmax - 1 <= tau*; Newton from below is monotone and
// lands exactly once inside the correct segment (~4-7 iters on Gaussian data).
// C is stationary in tau at the solution (dC/dtau = 1 - sum p = 0), so residual
// tau error eps costs only O(k*eps^2) in C.
__device__ __forceinline__ float sparse_c8(const float v[8]) {
    float zmax = v[0];
#pragma unroll
    for (int i = 1; i < 8; i++) zmax = fmaxf(zmax, v[i]);
    zmax = wredMax(zmax);
    float tau = zmax - 1.0f;
#pragma unroll 1
    for (int it = 0; it < 24; ++it) {
        float sl = 0.0f, kl = 0.0f;
#pragma unroll
        for (int i = 0; i < 8; i++) {
            float d = v[i] - tau;
            if (d > 0.0f) { sl += d; kl += 1.0f; }
        }
#pragma unroll
        for (int o = 16; o; o >>= 1) {
            sl += __shfl_xor_sync(0xffffffffu, sl, o);
            kl += __shfl_xor_sync(0xffffffffu, kl, o);
        }
        float f = sl - 1.0f;
        if (f <= 1e-6f) break;            // warp-uniform
        tau += __fdividef(f, kl);         // kl >= 1 while f > 0
    }
    float s2 = 0.0f;
#pragma unroll
    for (int i = 0; i < 8; i++) {
        float p = fmaxf(v[i] - tau, 0.0f);
        s2 = fmaf(p, p, s2);
    }
    s2 = wredSum(s2);
    return tau + 0.5f * s2 + 0.5f;
}

__device__ __forceinline__ void load_row8(const float* __restrict__ z, int lane, float v[8]) {
    const float4* z4 = reinterpret_cast<const float4*>(z);
    float4 a = z4[lane];
    float4 b = z4[lane + 32];
    v[0] = a.x; v[1] = a.y; v[2] = a.z; v[3] = a.w;
    v[4] = b.x; v[5] = b.y; v[6] = b.z; v[7] = b.w;
}

// -------- K1: per-row C for all 65536 rows of T --------
__global__ void __launch_bounds__(256) k_rowconst_T(const float* __restrict__ T) {
    int warp = (blockIdx.x * blockDim.x + threadIdx.x) >> 5;
    int lane = threadIdx.x & 31;
    float v[8];
    load_row8(T + (size_t)warp * SS, lane, v);
    float c = sparse_c8(v);
    if (lane == 0) g_cT[warp] = c;
}

// -------- K2: C for E rows, alpha, omega --------
__global__ void __launch_bounds__(256) k_small(const float* __restrict__ E,
                                               const float* __restrict__ al,
                                               const float* __restrict__ om) {
    int warp = (blockIdx.x * blockDim.x + threadIdx.x) >> 5;
    int lane = threadIdx.x & 31;
    float v[8];
    if (warp < SS) {
        load_row8(E + (size_t)warp * SS, lane, v);
        float c = sparse_c8(v);
        if (lane == 0) g_cE[warp] = c;
    } else if (warp == SS) {
        load_row8(al, lane, v);
        float c = sparse_c8(v);
#pragma unroll
        for (int i = 0; i < 8; i++) g_LAl[lane + 32 * i] = c - al[lane + 32 * i];
    } else if (warp == SS + 1) {
        load_row8(om, lane, v);
        float c = sparse_c8(v);
#pragma unroll
        for (int i = 0; i < 8; i++) g_c0[lane + 32 * i] = c - om[lane + 32 * i];
    }
}

// -------- K3: G[x][q] --------
__global__ void __launch_bounds__(256) k_gtab(const float* __restrict__ E) {
    int x = blockIdx.x, q = threadIdx.x;
    g_Gtab[x * SS + q] = g_cE[q] - E[q * SS + x] + g_cT[q * SS + x];
}

// -------- K4: M[x][n][q] = bf16(exp(-T[q][x][n])) --------
__global__ void __launch_bounds__(256) k_buildM(const float* __restrict__ T) {
    __shared__ float tile[32][33];
    int x  = blockIdx.z;
    int q0 = blockIdx.x << 5, n0 = blockIdx.y << 5;
    int tx = threadIdx.x, ty = threadIdx.y;
#pragma unroll
    for (int i = 0; i < 32; i += 8) {
        int q = q0 + ty + i;
        tile[ty + i][tx] = T[(unsigned)q * 65536u + (unsigned)x * 256u + n0 + tx];
    }
    __syncthreads();
#pragma unroll
    for (int i = 0; i < 32; i += 8) {
        int n = n0 + ty + i;
        g_M[(size_t)x * 65536u + (size_t)n * 256u + q0 + tx] =
            __float2bfloat16(exp_poly(-tile[tx][ty + i]));
    }
}

// -------- cluster primitives --------
__device__ __forceinline__ unsigned smem_u32(const void* p) {
    return (unsigned)__cvta_generic_to_shared(p);
}
__device__ __forceinline__ unsigned mapa_u32(unsigned local_smem, unsigned target_rank) {
    unsigned remote;
    asm volatile("mapa.shared::cluster.u32 %0, %1, %2;"
                 : "=r"(remote) : "r"(local_smem), "r"(target_rank));
    return remote;
}
__device__ __forceinline__ void cluster_sync_() {
    asm volatile("barrier.cluster.arrive.aligned;" ::: "memory");
    asm volatile("barrier.cluster.wait.aligned;"   ::: "memory");
}
__device__ __forceinline__ void mbar_wait_acq(unsigned addr, unsigned parity) {
    asm volatile(
        "{\n\t.reg .pred P;\n\t"
        "WAITLOOP_%=:\n\t"
        "mbarrier.try_wait.parity.acquire.cluster.shared::cta.b64 P, [%0], %1, 0x989680;\n\t"
        "@P bra.uni WAITDONE_%=;\n\t"
        "bra.uni WAITLOOP_%=;\n\t"
        "WAITDONE_%=:\n\t}"
        :: "r"(addr), "r"(parity) : "memory");
}

// -------- K5: backward recursion, 2 batches interleaved per 8-CTA cluster ---
__global__ void __cluster_dims__(CLUSTER, 1, 1) __launch_bounds__(256, 1)
k_forward(const int* __restrict__ xs) {
    __shared__ float sbufA[2][SS];                 // chart, batch A, dbl buffered
    __shared__ float sbufB[2][SS];                 // chart, batch B
    __shared__ __align__(16) float se2[8 * 36];    // shared between sub-steps:
    __shared__ float spart[8][32];                 //   every use is bracketed by
                                                   //   the step's own 2 barriers
    __shared__ int   sxA[LL], sxB[LL];
    __shared__ float sG[SS * 32];
    __shared__ __align__(8) unsigned long long smbarA[2], smbarB[2];

    const int tid  = threadIdx.x;
    const int lane = tid & 31, wid = tid >> 5;
    const unsigned rank = (unsigned)(blockIdx.x & (CLUSTER - 1));
    const int cid = blockIdx.x >> 3;
    const int bA = 2 * cid, bB = 2 * cid + 1;
    const int q0 = (int)rank * 32;

    for (int i = tid; i < LL; i += 256) {
        sxA[i] = xs[bA * LL + i];
        sxB[i] = xs[bB * LL + i];
    }
    for (int i = tid; i < SS * 32; i += 256) {
        int x = i >> 5, l = i & 31;
        sG[i] = g_Gtab[x * SS + q0 + l];
    }
    {
        float c0 = g_c0[tid];
        sbufA[0][tid] = c0;
        sbufB[0][tid] = c0;
    }
    if (tid == 0) {
#pragma unroll
        for (int i = 0; i < 2; i++) {
            asm volatile("mbarrier.init.shared.b64 [%0], %1;"
                         :: "r"(smem_u32(&smbarA[i])), "r"(8) : "memory");
            asm volatile("mbarrier.init.shared.b64 [%0], %1;"
                         :: "r"(smem_u32(&smbarB[i])), "r"(8) : "memory");
        }
    }
    __syncthreads();
    cluster_sync_();   // init + mbarriers visible cluster-wide

    // warp w ships this CTA's q-chunk + arrival to peer CTA w
    const unsigned barA0_loc = smem_u32(&smbarA[0]);
    const unsigned barA1_loc = smem_u32(&smbarA[1]);
    const unsigned barB0_loc = smem_u32(&smbarB[0]);
    const unsigned barB1_loc = smem_u32(&smbarB[1]);
    const unsigned barA_rem0 = mapa_u32(barA0_loc, (unsigned)wid);
    const unsigned barA_rem1 = mapa_u32(barA1_loc, (unsigned)wid);
    const unsigned barB_rem0 = mapa_u32(barB0_loc, (unsigned)wid);
    const unsigned barB_rem1 = mapa_u32(barB1_loc, (unsigned)wid);
    const unsigned chA_rem0  = mapa_u32(smem_u32(&sbufA[0][q0 + lane]), (unsigned)wid);
    const unsigned chA_rem1  = mapa_u32(smem_u32(&sbufA[1][q0 + lane]), (unsigned)wid);
    const unsigned chB_rem0  = mapa_u32(smem_u32(&sbufB[0][q0 + lane]), (unsigned)wid);
    const unsigned chB_rem1  = mapa_u32(smem_u32(&sbufB[1][q0 + lane]), (unsigned)wid);

    unsigned short mA0[32], mA1[32], mB0[32], mB1[32];

#define PREFETCH(dst, xval) do {                                                   \
    const unsigned short* _mp = (const unsigned short*)g_M                         \
        + (((unsigned)(xval)) << 16) + ((unsigned)wid << 8) + (unsigned)(q0+lane); \
    _Pragma("unroll")                                                              \
    for (int _j = 0; _j < 32; _j++) dst[_j] = __ldg(_mp + (_j << 11));             \
} while (0)

    // All SBUF[P] reads hoisted before the first __syncthreads (2-buffer safety
    // vs cross-CTA skew, same argument as before; interleaving only adds slack).
#define STEP_COMPUTE(SBUF, P, CUR, CHREM, BARREM, XV) do {                         \
    const int _x = (XV);                                                           \
    float cmax  = SBUF[P][0];                                                      \
    float c     = SBUF[P][tid];                                                    \
    float cpass = SBUF[P][q0 + lane];                                              \
    se2[(tid & 7) * 36 + (tid >> 3)] = __expf(c - cmax);                           \
    __syncthreads();                                                               \
    float a0 = 0.f, a1 = 0.f, a2 = 0.f, a3 = 0.f;                                  \
    const float4* _sv4 = (const float4*)&se2[wid * 36];                            \
    _Pragma("unroll")                                                              \
    for (int _j = 0; _j < 8; _j++) {                                               \
        float4 _sv = _sv4[_j];                                                     \
        a0 = fmaf(__uint_as_float((unsigned)CUR[4*_j+0] << 16), _sv.x, a0);        \
        a1 = fmaf(__uint_as_float((unsigned)CUR[4*_j+1] << 16), _sv.y, a1);        \
        a2 = fmaf(__uint_as_float((unsigned)CUR[4*_j+2] << 16), _sv.z, a2);        \
        a3 = fmaf(__uint_as_float((unsigned)CUR[4*_j+3] << 16), _sv.w, a3);        \
    }                                                                              \
    spart[wid][lane] = (a0 + a1) + (a2 + a3);                                      \
    __syncthreads();                                                               \
    float ssum = 0.f;                                                              \
    _Pragma("unroll")                                                              \
    for (int _g = 0; _g < 8; _g++) ssum += spart[_g][lane];                        \
    float nc = (_x != 0) ? (sG[(_x << 5) + lane] + __logf(ssum) + cmax) : cpass;   \
    asm volatile("st.shared::cluster.f32 [%0], %1;"                                \
                 :: "r"(CHREM), "f"(nc) : "memory");                               \
    __syncwarp();                                                                  \
    if (lane == 0)                                                                 \
        asm volatile("mbarrier.arrive.release.cluster.shared::cluster.b64 _, [%0];"\
                     :: "r"(BARREM) : "memory");                                   \
} while (0)

    PREFETCH(mA0, sxA[LL - 1]);
    PREFETCH(mB0, sxB[LL - 1]);

    unsigned phA0 = 0, phA1 = 0, phB0 = 0, phB1 = 0;
#pragma unroll 1
    for (int s = 0; s < LL; s += 2) {
        // A even: reads sbufA[0], writes peers' sbufA[1], arrives barA[1]
        PREFETCH(mA1, sxA[LL - 2 - s]);
        if (s) { mbar_wait_acq(barA0_loc, phA0); phA0 ^= 1; }
        STEP_COMPUTE(sbufA, 0, mA0, chA_rem1, barA_rem1, sxA[LL - 1 - s]);

        // B even (A's stores/arrivals fly underneath)
        PREFETCH(mB1, sxB[LL - 2 - s]);
        if (s) { mbar_wait_acq(barB0_loc, phB0); phB0 ^= 1; }
        STEP_COMPUTE(sbufB, 0, mB0, chB_rem1, barB_rem1, sxB[LL - 1 - s]);

        // A odd
        PREFETCH(mA0, (s + 2 < LL) ? sxA[LL - 3 - s] : 0);
        mbar_wait_acq(barA1_loc, phA1); phA1 ^= 1;
        STEP_COMPUTE(sbufA, 1, mA1, chA_rem0, barA_rem0, sxA[LL - 2 - s]);

        // B odd
        PREFETCH(mB0, (s + 2 < LL) ? sxB[LL - 3 - s] : 0);
        mbar_wait_acq(barB1_loc, phB1); phB1 ^= 1;
        STEP_COMPUTE(sbufB, 1, mB1, chB_rem0, barB_rem0, sxB[LL - 2 - s]);
    }
    // consume step-511 arrivals (writes landed in sbuf*[0]) in every CTA
    mbar_wait_acq(barA0_loc, phA0);
    mbar_wait_acq(barB0_loc, phB0);

    if (rank == 0 && wid < 2) {
        const float* cf = (wid == 0) ? sbufA[0] : sbufB[0];
        float vv[8];
        float m = -3.0e38f;
#pragma unroll
        for (int i = 0; i < 8; i++) {
            vv[i] = g_LAl[lane + 32 * i] + cf[lane + 32 * i];
            m = fmaxf(m, vv[i]);
        }
        m = wredMax(m);
        float sacc = 0.0f;
#pragma unroll
        for (int i = 0; i < 8; i++) sacc += __expf(vv[i] - m);
        sacc = wredSum(sacc);
        if (lane == 0) g_perseq[(wid == 0) ? bA : bB] = __logf(sacc) + m;
    }
    cluster_sync_();   // no CTA exits while remote ops may target it
#undef PREFETCH
#undef STEP_COMPUTE
}

// -------- K6: out = sum_b per_seq[b] --------
__global__ void k_final(float* __restrict__ out) {
    float v = (threadIdx.x < BB) ? g_perseq[threadIdx.x] : 0.0f;
    v = wredSum(v);
    if (threadIdx.x == 0) out[0] = v;
}

// ============================================================================
extern "C" void kernel_launch(void* const* d_in, const int* in_sizes, int n_in,
                              void* d_out, int out_size) {
    const int*   xs    = (const int*)d_in[0];
    const float* alpha = (const float*)d_in[1];
    const float* omega = (const float*)d_in[2];
    const float* E     = (const float*)d_in[3];
    const float* T     = (const float*)d_in[4];
    float* out = (float*)d_out;

    k_rowconst_T<<<(SS * SS) / 8, 256>>>(T);
    k_small<<<33, 256>>>(E, alpha, omega);
    k_gtab<<<SS, 256>>>(E);
    k_buildM<<<dim3(8, 8, SS), dim3(32, 8)>>>(T);
    k_forward<<<(BB / 2) * CLUSTER, 256>>>(xs);   // 8 clusters x 8 CTAs, 2 batches each
    k_final<<<1, 32>>>(out);
}

// round 8
// speedup vs baseline: 1.5842x; 1.5842x over previous
#include <cuda_runtime.h>
#include <cuda_bf16.h>
#include <cstdint>

// ============================================================================
// S = 256 states/vocab, B = 16 sequences, L = 512 tokens.
// sparsemax_loss_vec(z)[y] = C(z) - z[y], C(z) = tau + 0.5*sum(p^2) + 0.5
// Backward recurrence (log semiring):
//   c_t[q] = G[x][q] + log( sum_n exp(-T[q,x,n]) * exp(c_{t+1}[n] - cmax) ) + cmax
//   G[x][q] = cE[q] - E[q,x] + cT[q,x]
// out = sum_b LSE_q( (cA - alpha[q]) + c_0[b,q] ),  c_L[q] = cOmega - omega[q]
//
// k_forward: 8 clusters x 8 CTAs; each cluster interleaves TWO batches (A,B)
// so one batch's cross-CTA latency hides under the other's compute.
// Chart exchange uses st.async + mbarrier complete_tx (fused data+signal),
// waits are CTA-scope acquire. Register budget kept at R6 level (no spills).
// ============================================================================

#define SS 256
#define BB 16
#define LL 512
#define CLUSTER 8

// -------- device scratch --------
__device__ float          g_cT[SS * SS];
__device__ float          g_cE[SS];
__device__ float          g_Gtab[SS * SS];            // [x][q]
__device__ float          g_c0[SS];
__device__ float          g_LAl[SS];
__device__ __nv_bfloat16  g_M[(size_t)SS * SS * SS];  // [x][next][q] = exp(-T[q,x,next])
__device__ float          g_perseq[BB];

// -------- helpers --------
__device__ __forceinline__ float wredMax(float v) {
#pragma unroll
    for (int o = 16; o; o >>= 1) v = fmaxf(v, __shfl_xor_sync(0xffffffffu, v, o));
    return v;
}
__device__ __forceinline__ float wredSum(float v) {
#pragma unroll
    for (int o = 16; o; o >>= 1) v += __shfl_xor_sync(0xffffffffu, v, o);
    return v;
}

// MUFU-free exp (|x| <= ~0.8 here)
__device__ __forceinline__ float exp_poly(float x) {
    float y = x * 1.44269504088896341f;
    float n = rintf(y);
    float t = (y - n) * 0.6931471805599453f;
    float p = 1.98412698412698413e-4f;
    p = fmaf(p, t, 1.38888888888888889e-3f);
    p = fmaf(p, t, 8.33333333333333333e-3f);
    p = fmaf(p, t, 4.16666666666666667e-2f);
    p = fmaf(p, t, 1.66666666666666667e-1f);
    p = fmaf(p, t, 0.5f);
    p = fmaf(p, t, 1.0f);
    p = fmaf(p, t, 1.0f);
    return p * __int_as_float(((int)n + 127) << 23);
}

// C(z) via Newton on f(tau) = sum relu(z - tau) - 1 (convex, piecewise linear,
// decreasing); tau0 = zmax - 1 <= tau*, Newton from below is monotone. C is
// stationary in tau at the optimum, so residual tau error is quadratically
// damped in C. (Bit-identical output vs 14-iter bisection in R6/R7 runs.)
__device__ __forceinline__ float sparse_c8(const float v[8]) {
    float zmax = v[0];
#pragma unroll
    for (int i = 1; i < 8; i++) zmax = fmaxf(zmax, v[i]);
    zmax = wredMax(zmax);
    float tau = zmax - 1.0f;
#pragma unroll 1
    for (int it = 0; it < 24; ++it) {
        float sl = 0.0f, kl = 0.0f;
#pragma unroll
        for (int i = 0; i < 8; i++) {
            float d = v[i] - tau;
            if (d > 0.0f) { sl += d; kl += 1.0f; }
        }
#pragma unroll
        for (int o = 16; o; o >>= 1) {
            sl += __shfl_xor_sync(0xffffffffu, sl, o);
            kl += __shfl_xor_sync(0xffffffffu, kl, o);
        }
        float f = sl - 1.0f;
        if (f <= 1e-6f) break;            // warp-uniform
        tau += __fdividef(f, kl);         // kl >= 1 while f > 0
    }
    float s2 = 0.0f;
#pragma unroll
    for (int i = 0; i < 8; i++) {
        float p = fmaxf(v[i] - tau, 0.0f);
        s2 = fmaf(p, p, s2);
    }
    s2 = wredSum(s2);
    return tau + 0.5f * s2 + 0.5f;
}

__device__ __forceinline__ void load_row8(const float* __restrict__ z, int lane, float v[8]) {
    const float4* z4 = reinterpret_cast<const float4*>(z);
    float4 a = z4[lane];
    float4 b = z4[lane + 32];
    v[0] = a.x; v[1] = a.y; v[2] = a.z; v[3] = a.w;
    v[4] = b.x; v[5] = b.y; v[6] = b.z; v[7] = b.w;
}

// -------- K1: per-row C for all 65536 rows of T --------
__global__ void __launch_bounds__(256) k_rowconst_T(const float* __restrict__ T) {
    int warp = (blockIdx.x * blockDim.x + threadIdx.x) >> 5;
    int lane = threadIdx.x & 31;
    float v[8];
    load_row8(T + (size_t)warp * SS, lane, v);
    float c = sparse_c8(v);
    if (lane == 0) g_cT[warp] = c;
}

// -------- K2: C for E rows, alpha, omega --------
__global__ void __launch_bounds__(256) k_small(const float* __restrict__ E,
                                               const float* __restrict__ al,
                                               const float* __restrict__ om) {
    int warp = (blockIdx.x * blockDim.x + threadIdx.x) >> 5;
    int lane = threadIdx.x & 31;
    float v[8];
    if (warp < SS) {
        load_row8(E + (size_t)warp * SS, lane, v);
        float c = sparse_c8(v);
        if (lane == 0) g_cE[warp] = c;
    } else if (warp == SS) {
        load_row8(al, lane, v);
        float c = sparse_c8(v);
#pragma unroll
        for (int i = 0; i < 8; i++) g_LAl[lane + 32 * i] = c - al[lane + 32 * i];
    } else if (warp == SS + 1) {
        load_row8(om, lane, v);
        float c = sparse_c8(v);
#pragma unroll
        for (int i = 0; i < 8; i++) g_c0[lane + 32 * i] = c - om[lane + 32 * i];
    }
}

// -------- K3: G[x][q] --------
__global__ void __launch_bounds__(256) k_gtab(const float* __restrict__ E) {
    int x = blockIdx.x, q = threadIdx.x;
    g_Gtab[x * SS + q] = g_cE[q] - E[q * SS + x] + g_cT[q * SS + x];
}

// -------- K4: M[x][n][q] = bf16(exp(-T[q][x][n])) --------
__global__ void __launch_bounds__(256) k_buildM(const float* __restrict__ T) {
    __shared__ float tile[32][33];
    int x  = blockIdx.z;
    int q0 = blockIdx.x << 5, n0 = blockIdx.y << 5;
    int tx = threadIdx.x, ty = threadIdx.y;
#pragma unroll
    for (int i = 0; i < 32; i += 8) {
        int q = q0 + ty + i;
        tile[ty + i][tx] = T[(unsigned)q * 65536u + (unsigned)x * 256u + n0 + tx];
    }
    __syncthreads();
#pragma unroll
    for (int i = 0; i < 32; i += 8) {
        int n = n0 + ty + i;
        g_M[(size_t)x * 65536u + (size_t)n * 256u + q0 + tx] =
            __float2bfloat16(exp_poly(-tile[tx][ty + i]));
    }
}

// -------- cluster primitives --------
__device__ __forceinline__ unsigned smem_u32(const void* p) {
    return (unsigned)__cvta_generic_to_shared(p);
}
__device__ __forceinline__ unsigned mapa_u32(unsigned local_smem, unsigned target_rank) {
    unsigned remote;
    asm volatile("mapa.shared::cluster.u32 %0, %1, %2;"
                 : "=r"(remote) : "r"(local_smem), "r"(target_rank));
    return remote;
}
__device__ __forceinline__ void cluster_sync_() {
    asm volatile("barrier.cluster.arrive.aligned;" ::: "memory");
    asm volatile("barrier.cluster.wait.aligned;"   ::: "memory");
}
// CTA-scope acquire wait: data arrives via st.async complete_tx, whose
// mbarrier completion guarantees visibility to acquiring waiters (TMA pattern).
__device__ __forceinline__ void mbar_wait_cta(unsigned addr, unsigned parity) {
    asm volatile(
        "{\n\t.reg .pred P;\n\t"
        "WAITLOOP_%=:\n\t"
        "mbarrier.try_wait.parity.acquire.cta.shared::cta.b64 P, [%0], %1, 0x989680;\n\t"
        "@P bra.uni WAITDONE_%=;\n\t"
        "bra.uni WAITLOOP_%=;\n\t"
        "WAITDONE_%=:\n\t}"
        :: "r"(addr), "r"(parity) : "memory");
}

// -------- K5: backward recursion, 2 batches interleaved per 8-CTA cluster ---
__global__ void __cluster_dims__(CLUSTER, 1, 1) __launch_bounds__(256, 1)
k_forward(const int* __restrict__ xs) {
    __shared__ float sbufA[2][SS];                 // chart, batch A, dbl buffered
    __shared__ float sbufB[2][SS];                 // chart, batch B
    __shared__ __align__(16) float se2[8 * 36];    // shared between sub-steps
    __shared__ float spart[8][32];                 //   (bracketed by each step's
                                                   //    own two __syncthreads)
    __shared__ int   sxA[LL], sxB[LL];
    __shared__ float sG[SS * 32];
    __shared__ __align__(8) unsigned long long smbarA[2], smbarB[2];

    const int tid  = threadIdx.x;
    const int lane = tid & 31, wid = tid >> 5;
    const unsigned rank = (unsigned)(blockIdx.x & (CLUSTER - 1));
    const int cid = blockIdx.x >> 3;
    const int bA = 2 * cid, bB = 2 * cid + 1;
    const int q0 = (int)rank * 32;

    for (int i = tid; i < LL; i += 256) {
        sxA[i] = xs[bA * LL + i];
        sxB[i] = xs[bB * LL + i];
    }
    for (int i = tid; i < SS * 32; i += 256) {
        int x = i >> 5, l = i & 31;
        sG[i] = g_Gtab[x * SS + q0 + l];
    }
    {
        float c0 = g_c0[tid];
        sbufA[0][tid] = c0;
        sbufB[0][tid] = c0;
    }
    if (tid == 0) {
#pragma unroll
        for (int i = 0; i < 2; i++) {
            asm volatile("mbarrier.init.shared.b64 [%0], %1;"
                         :: "r"(smem_u32(&smbarA[i])), "r"(1) : "memory");
            asm volatile("mbarrier.init.shared.b64 [%0], %1;"
                         :: "r"(smem_u32(&smbarB[i])), "r"(1) : "memory");
        }
    }
    __syncthreads();
    cluster_sync_();   // inits visible cluster-wide before any st.async

    // warp w ships this CTA's q-chunk to peer CTA w (data+tx signal fused)
    const unsigned barA0_loc = smem_u32(&smbarA[0]);
    const unsigned barA1_loc = smem_u32(&smbarA[1]);
    const unsigned barB0_loc = smem_u32(&smbarB[0]);
    const unsigned barB1_loc = smem_u32(&smbarB[1]);
    const unsigned barA_rem0 = mapa_u32(barA0_loc, (unsigned)wid);
    const unsigned barA_rem1 = mapa_u32(barA1_loc, (unsigned)wid);
    const unsigned barB_rem0 = mapa_u32(barB0_loc, (unsigned)wid);
    const unsigned barB_rem1 = mapa_u32(barB1_loc, (unsigned)wid);
    const unsigned chA_rem0  = mapa_u32(smem_u32(&sbufA[0][q0 + lane]), (unsigned)wid);
    const unsigned chA_rem1  = mapa_u32(smem_u32(&sbufA[1][q0 + lane]), (unsigned)wid);
    const unsigned chB_rem0  = mapa_u32(smem_u32(&sbufB[0][q0 + lane]), (unsigned)wid);
    const unsigned chB_rem1  = mapa_u32(smem_u32(&sbufB[1][q0 + lane]), (unsigned)wid);

    // ONE prefetch buffer per batch: 64 u16 regs total (R6 budget, no spills)
    unsigned short mA[32], mB[32];

#define PREFETCH(dst, xval) do {                                                   \
    const unsigned short* _mp = (const unsigned short*)g_M                         \
        + (((unsigned)(xval)) << 16) + ((unsigned)wid << 8) + (unsigned)(q0+lane); \
    _Pragma("unroll")                                                              \
    for (int _j = 0; _j < 32; _j++) dst[_j] = __ldg(_mp + (_j << 11));             \
} while (0)

// thread0 declares this phase's expected incoming bytes on the RECEIVING
// barrier (8 CTAs x 32 lanes x 4B = 1024). Counter is order-independent vs
// the incoming stores; init count=1 means the phase can't complete before
// this arrive lands.
#define EXPECT(BARLOC) do {                                                        \
    if (tid == 0)                                                                  \
        asm volatile("mbarrier.arrive.expect_tx.shared.b64 _, [%0], %1;"           \
                     :: "r"(BARLOC), "r"(1024) : "memory");                        \
} while (0)

    // All SBUF[P] reads hoisted before the first __syncthreads. 2-buffer reuse
    // is safe: any CTA's step-(s+1) sends are behind its step-(s+1)
    // __syncthreads, which orders after all its hoisted reads of sbuf[NP].
#define STEP_COMPUTE(SBUF, P, CUR, CHREM, BARREM, XV) do {                         \
    const int _x = (XV);                                                           \
    float cmax  = SBUF[P][0];                                                      \
    float c     = SBUF[P][tid];                                                    \
    float cpass = SBUF[P][q0 + lane];                                              \
    se2[(tid & 7) * 36 + (tid >> 3)] = __expf(c - cmax);                           \
    __syncthreads();                                                               \
    float a0 = 0.f, a1 = 0.f, a2 = 0.f, a3 = 0.f;                                  \
    const float4* _sv4 = (const float4*)&se2[wid * 36];                            \
    _Pragma("unroll")                                                              \
    for (int _j = 0; _j < 8; _j++) {                                               \
        float4 _sv = _sv4[_j];                                                     \
        a0 = fmaf(__uint_as_float((unsigned)CUR[4*_j+0] << 16), _sv.x, a0);        \
        a1 = fmaf(__uint_as_float((unsigned)CUR[4*_j+1] << 16), _sv.y, a1);        \
        a2 = fmaf(__uint_as_float((unsigned)CUR[4*_j+2] << 16), _sv.z, a2);        \
        a3 = fmaf(__uint_as_float((unsigned)CUR[4*_j+3] << 16), _sv.w, a3);        \
    }                                                                              \
    spart[wid][lane] = (a0 + a1) + (a2 + a3);                                      \
    __syncthreads();                                                               \
    float ssum = 0.f;                                                              \
    _Pragma("unroll")                                                              \
    for (int _g = 0; _g < 8; _g++) ssum += spart[_g][lane];                        \
    float nc = (_x != 0) ? (sG[(_x << 5) + lane] + __logf(ssum) + cmax) : cpass;   \
    asm volatile("st.async.shared::cluster.mbarrier::complete_tx::bytes.f32 "      \
                 "[%0], %1, [%2];"                                                 \
                 :: "r"(CHREM), "f"(nc), "r"(BARREM) : "memory");                  \
} while (0)

    PREFETCH(mA, sxA[LL - 1]);
    PREFETCH(mB, sxB[LL - 1]);

    unsigned phA0 = 0, phA1 = 0, phB0 = 0, phB1 = 0;
#pragma unroll 1
    for (int s = 0; s < LL; s += 2) {
        // A even: reads sbufA[0], sends into peers' sbufA[1]/barA[1]
        EXPECT(barA1_loc);
        if (s) { mbar_wait_cta(barA0_loc, phA0); phA0 ^= 1; }
        STEP_COMPUTE(sbufA, 0, mA, chA_rem1, barA_rem1, sxA[LL - 1 - s]);
        PREFETCH(mA, sxA[LL - 2 - s]);                    // x for A step s+1

        // B even (A's stores + prefetch fly underneath)
        EXPECT(barB1_loc);
        if (s) { mbar_wait_cta(barB0_loc, phB0); phB0 ^= 1; }
        STEP_COMPUTE(sbufB, 0, mB, chB_rem1, barB_rem1, sxB[LL - 1 - s]);
        PREFETCH(mB, sxB[LL - 2 - s]);

        // A odd: reads sbufA[1], sends into peers' sbufA[0]/barA[0]
        EXPECT(barA0_loc);
        mbar_wait_cta(barA1_loc, phA1); phA1 ^= 1;
        STEP_COMPUTE(sbufA, 1, mA, chA_rem0, barA_rem0, sxA[LL - 2 - s]);
        PREFETCH(mA, (s + 2 < LL) ? sxA[LL - 3 - s] : 0); // dummy ok at end

        // B odd
        EXPECT(barB0_loc);
        mbar_wait_cta(barB1_loc, phB1); phB1 ^= 1;
        STEP_COMPUTE(sbufB, 1, mB, chB_rem0, barB_rem0, sxB[LL - 2 - s]);
        PREFETCH(mB, (s + 2 < LL) ? sxB[LL - 3 - s] : 0);
    }
    // consume step-511 arrivals (data landed in sbuf*[0]) in every CTA
    mbar_wait_cta(barA0_loc, phA0);
    mbar_wait_cta(barB0_loc, phB0);

    if (rank == 0 && wid < 2) {
        const float* cf = (wid == 0) ? sbufA[0] : sbufB[0];
        float vv[8];
        float m = -3.0e38f;
#pragma unroll
        for (int i = 0; i < 8; i++) {
            vv[i] = g_LAl[lane + 32 * i] + cf[lane + 32 * i];
            m = fmaxf(m, vv[i]);
        }
        m = wredMax(m);
        float sacc = 0.0f;
#pragma unroll
        for (int i = 0; i < 8; i++) sacc += __expf(vv[i] - m);
        sacc = wredSum(sacc);
        if (lane == 0) g_perseq[(wid == 0) ? bA : bB] = __logf(sacc) + m;
    }
    cluster_sync_();   // no CTA exits while remote ops may target it
#undef PREFETCH
#undef EXPECT
#undef STEP_COMPUTE
}

// -------- K6: out = sum_b per_seq[b] --------
__global__ void k_final(float* __restrict__ out) {
    float v = (threadIdx.x < BB) ? g_perseq[threadIdx.x] : 0.0f;
    v = wredSum(v);
    if (threadIdx.x == 0) out[0] = v;
}

// ============================================================================
extern "C" void kernel_launch(void* const* d_in, const int* in_sizes, int n_in,
                              void* d_out, int out_size) {
    const int*   xs    = (const int*)d_in[0];
    const float* alpha = (const float*)d_in[1];
    const float* omega = (const float*)d_in[2];
    const float* E     = (const float*)d_in[3];
    const float* T     = (const float*)d_in[4];
    float* out = (float*)d_out;

    k_rowconst_T<<<(SS * SS) / 8, 256>>>(T);
    k_small<<<33, 256>>>(E, alpha, omega);
    k_gtab<<<SS, 256>>>(E);
    k_buildM<<<dim3(8, 8, SS), dim3(32, 8)>>>(T);
    k_forward<<<(BB / 2) * CLUSTER, 256>>>(xs);   // 8 clusters x 8 CTAs, 2 batches each
    k_final<<<1, 32>>>(out);
}

// round 9
// speedup vs baseline: 2.1941x; 1.3850x over previous
#include <cuda_runtime.h>
#include <cuda_bf16.h>
#include <cstdint>

// ============================================================================
// S = 256 states/vocab, B = 16 sequences, L = 512 tokens.
// sparsemax_loss_vec(z)[y] = C(z) - z[y], C(z) = tau + 0.5*sum(p^2) + 0.5
// Backward recurrence (log semiring):
//   c_t[q] = G[x][q] + log( sum_n exp(-T[q,x,n]) * exp(c_{t+1}[n] - cmax) ) + cmax
//   G[x][q] = cE[q] - E[q,x] + cT[q,x]
// out = sum_b LSE_q( (cA - alpha[q]) + c_0[b,q] ),  c_L[q] = cOmega - omega[q]
//
// k_forward R9: one batch = a 2-CTA cluster (512 thr/CTA, 32 SMs total).
// Each CTA owns 128 q, streams 64KB of M per step, and exchanges only 128
// floats with ONE peer per step (st.async + complete_tx). M and G for the
// next step are register-prefetched before the reduction, so the L1/L2 load
// stream never pauses across the pairwise wait.
// ============================================================================

#define SS 256
#define BB 16
#define LL 512
#define NT 512          // threads per CTA (16 warps) -> 128 regs/thread ceiling

// -------- device scratch --------
__device__ float          g_cT[SS * SS];
__device__ float          g_cE[SS];
__device__ float          g_Gtab[SS * SS];            // [x][q]
__device__ float          g_c0[SS];
__device__ float          g_LAl[SS];
__device__ __nv_bfloat16  g_M[(size_t)SS * SS * SS];  // [x][next][q] = exp(-T[q,x,next])
__device__ float          g_perseq[BB];

// -------- helpers --------
__device__ __forceinline__ float wredMax(float v) {
#pragma unroll
    for (int o = 16; o; o >>= 1) v = fmaxf(v, __shfl_xor_sync(0xffffffffu, v, o));
    return v;
}
__device__ __forceinline__ float wredSum(float v) {
#pragma unroll
    for (int o = 16; o; o >>= 1) v += __shfl_xor_sync(0xffffffffu, v, o);
    return v;
}

// MUFU-free exp (|x| <= ~0.8 here)
__device__ __forceinline__ float exp_poly(float x) {
    float y = x * 1.44269504088896341f;
    float n = rintf(y);
    float t = (y - n) * 0.6931471805599453f;
    float p = 1.98412698412698413e-4f;
    p = fmaf(p, t, 1.38888888888888889e-3f);
    p = fmaf(p, t, 8.33333333333333333e-3f);
    p = fmaf(p, t, 4.16666666666666667e-2f);
    p = fmaf(p, t, 1.66666666666666667e-1f);
    p = fmaf(p, t, 0.5f);
    p = fmaf(p, t, 1.0f);
    p = fmaf(p, t, 1.0f);
    return p * __int_as_float(((int)n + 127) << 23);
}

// C(z) via Newton on f(tau) = sum relu(z - tau) - 1 (bit-identical output vs
// bisection across R6-R8 runs; C is stationary in tau at the optimum).
__device__ __forceinline__ float sparse_c8(const float v[8]) {
    float zmax = v[0];
#pragma unroll
    for (int i = 1; i < 8; i++) zmax = fmaxf(zmax, v[i]);
    zmax = wredMax(zmax);
    float tau = zmax - 1.0f;
#pragma unroll 1
    for (int it = 0; it < 24; ++it) {
        float sl = 0.0f, kl = 0.0f;
#pragma unroll
        for (int i = 0; i < 8; i++) {
            float d = v[i] - tau;
            if (d > 0.0f) { sl += d; kl += 1.0f; }
        }
#pragma unroll
        for (int o = 16; o; o >>= 1) {
            sl += __shfl_xor_sync(0xffffffffu, sl, o);
            kl += __shfl_xor_sync(0xffffffffu, kl, o);
        }
        float f = sl - 1.0f;
        if (f <= 1e-6f) break;            // warp-uniform
        tau += __fdividef(f, kl);
    }
    float s2 = 0.0f;
#pragma unroll
    for (int i = 0; i < 8; i++) {
        float p = fmaxf(v[i] - tau, 0.0f);
        s2 = fmaf(p, p, s2);
    }
    s2 = wredSum(s2);
    return tau + 0.5f * s2 + 0.5f;
}

__device__ __forceinline__ void load_row8(const float* __restrict__ z, int lane, float v[8]) {
    const float4* z4 = reinterpret_cast<const float4*>(z);
    float4 a = z4[lane];
    float4 b = z4[lane + 32];
    v[0] = a.x; v[1] = a.y; v[2] = a.z; v[3] = a.w;
    v[4] = b.x; v[5] = b.y; v[6] = b.z; v[7] = b.w;
}

// -------- K1: per-row C for all 65536 rows of T --------
__global__ void __launch_bounds__(256) k_rowconst_T(const float* __restrict__ T) {
    int warp = (blockIdx.x * blockDim.x + threadIdx.x) >> 5;
    int lane = threadIdx.x & 31;
    float v[8];
    load_row8(T + (size_t)warp * SS, lane, v);
    float c = sparse_c8(v);
    if (lane == 0) g_cT[warp] = c;
}

// -------- K2: C for E rows, alpha, omega --------
__global__ void __launch_bounds__(256) k_small(const float* __restrict__ E,
                                               const float* __restrict__ al,
                                               const float* __restrict__ om) {
    int warp = (blockIdx.x * blockDim.x + threadIdx.x) >> 5;
    int lane = threadIdx.x & 31;
    float v[8];
    if (warp < SS) {
        load_row8(E + (size_t)warp * SS, lane, v);
        float c = sparse_c8(v);
        if (lane == 0) g_cE[warp] = c;
    } else if (warp == SS) {
        load_row8(al, lane, v);
        float c = sparse_c8(v);
#pragma unroll
        for (int i = 0; i < 8; i++) g_LAl[lane + 32 * i] = c - al[lane + 32 * i];
    } else if (warp == SS + 1) {
        load_row8(om, lane, v);
        float c = sparse_c8(v);
#pragma unroll
        for (int i = 0; i < 8; i++) g_c0[lane + 32 * i] = c - om[lane + 32 * i];
    }
}

// -------- K3: G[x][q] --------
__global__ void __launch_bounds__(256) k_gtab(const float* __restrict__ E) {
    int x = blockIdx.x, q = threadIdx.x;
    g_Gtab[x * SS + q] = g_cE[q] - E[q * SS + x] + g_cT[q * SS + x];
}

// -------- K4: M[x][n][q] = bf16(exp(-T[q][x][n])) --------
__global__ void __launch_bounds__(256) k_buildM(const float* __restrict__ T) {
    __shared__ float tile[32][33];
    int x  = blockIdx.z;
    int q0 = blockIdx.x << 5, n0 = blockIdx.y << 5;
    int tx = threadIdx.x, ty = threadIdx.y;
#pragma unroll
    for (int i = 0; i < 32; i += 8) {
        int q = q0 + ty + i;
        tile[ty + i][tx] = T[(unsigned)q * 65536u + (unsigned)x * 256u + n0 + tx];
    }
    __syncthreads();
#pragma unroll
    for (int i = 0; i < 32; i += 8) {
        int n = n0 + ty + i;
        g_M[(size_t)x * 65536u + (size_t)n * 256u + q0 + tx] =
            __float2bfloat16(exp_poly(-tile[tx][ty + i]));
    }
}

// -------- cluster primitives --------
__device__ __forceinline__ unsigned smem_u32(const void* p) {
    return (unsigned)__cvta_generic_to_shared(p);
}
__device__ __forceinline__ unsigned mapa_u32(unsigned local_smem, unsigned target_rank) {
    unsigned remote;
    asm volatile("mapa.shared::cluster.u32 %0, %1, %2;"
                 : "=r"(remote) : "r"(local_smem), "r"(target_rank));
    return remote;
}
__device__ __forceinline__ void cluster_sync_() {
    asm volatile("barrier.cluster.arrive.aligned;" ::: "memory");
    asm volatile("barrier.cluster.wait.aligned;"   ::: "memory");
}
// CTA-scope acquire wait; incoming data is via st.async complete_tx whose
// barrier completion guarantees visibility to acquiring waiters.
__device__ __forceinline__ void mbar_wait_cta(unsigned addr, unsigned parity) {
    asm volatile(
        "{\n\t.reg .pred P;\n\t"
        "WAITLOOP_%=:\n\t"
        "mbarrier.try_wait.parity.acquire.cta.shared::cta.b64 P, [%0], %1, 0x989680;\n\t"
        "@P bra.uni WAITDONE_%=;\n\t"
        "bra.uni WAITLOOP_%=;\n\t"
        "WAITDONE_%=:\n\t}"
        :: "r"(addr), "r"(parity) : "memory");
}

// -------- K5: backward recursion, one batch per 2-CTA cluster --------------
// CTA rank r owns q in [128r, 128r+128). Warp w (0..15) covers n = 16w..16w+15,
// lane covers a q-quad (4 consecutive q). Per step: exchange 128 floats with
// the single peer CTA; everything else is CTA-local.
__global__ void __cluster_dims__(2, 1, 1) __launch_bounds__(NT, 1)
k_forward(const int* __restrict__ xs) {
    __shared__ float cbuf[2][SS];            // full chart, double buffered
    __shared__ __align__(16) float se[SS];   // exp(c - cmax)
    __shared__ __align__(16) float spart[16 * 128];  // 16 n-groups x 128 q
    __shared__ int   sx[LL];
    __shared__ __align__(8) unsigned long long bars[2];

    const int tid  = threadIdx.x;
    const int lane = tid & 31, wid = tid >> 5;
    const unsigned rank = (unsigned)(blockIdx.x & 1);
    const unsigned peer = rank ^ 1u;
    const int b  = blockIdx.x >> 1;
    const int qbase = (int)rank * 128;

    if (tid < LL) sx[tid] = xs[b * LL + tid];
    if (tid < SS) cbuf[0][tid] = g_c0[tid];
    if (tid == 0) {
        asm volatile("mbarrier.init.shared.b64 [%0], %1;"
                     :: "r"(smem_u32(&bars[0])), "r"(1) : "memory");
        asm volatile("mbarrier.init.shared.b64 [%0], %1;"
                     :: "r"(smem_u32(&bars[1])), "r"(1) : "memory");
    }
    __syncthreads();
    cluster_sync_();   // inits visible before any st.async

    const unsigned bar0_loc = smem_u32(&bars[0]);
    const unsigned bar1_loc = smem_u32(&bars[1]);
    const unsigned bar_rem0 = mapa_u32(bar0_loc, peer);
    const unsigned bar_rem1 = mapa_u32(bar1_loc, peer);
    // send target: same global q slot in the peer's chart buffers (tid < 128)
    const unsigned ch_rem0  = mapa_u32(smem_u32(&cbuf[0][qbase + tid]), peer);
    const unsigned ch_rem1  = mapa_u32(smem_u32(&cbuf[1][qbase + tid]), peer);

    const __nv_bfloat16* __restrict__ mb = g_M;
    uint2 PF[16];                            // 16 n x 4 q of bf16 (32 regs)
    float gcur = 0.0f, gnext;

#define PFETCH(xv) do {                                                           \
    const uint2* _mp = (const uint2*)(mb + ((size_t)(unsigned)(xv) << 16)         \
                         + ((unsigned)wid << 12) + (unsigned)(qbase + (lane<<2)));\
    _Pragma("unroll")                                                             \
    for (int _j = 0; _j < 16; _j++) PF[_j] = __ldg(_mp + (_j << 6));              \
} while (0)

    {
        int x0 = sx[LL - 1];
        PFETCH(x0);
        if (tid < 128) gcur = g_Gtab[x0 * SS + qbase + tid];
    }

    unsigned ph0 = 0, ph1 = 0;
#pragma unroll 1
    for (int s = 0; s < LL; ++s) {
        const int p = s & 1, np = p ^ 1;
        const int x = sx[LL - 1 - s];

        // arm receive barrier for this step's incoming peer half (128 x 4B).
        // tx-counter is order-independent; previous phase of bars[np] was
        // already consumed (program order), so re-arming is safe.
        if (tid == 0)
            asm volatile("mbarrier.arrive.expect_tx.shared.b64 _, [%0], %1;"
                         :: "r"(np ? bar1_loc : bar0_loc), "r"(512) : "memory");

        if (s) {
            if (p) { mbar_wait_cta(bar1_loc, ph1); ph1 ^= 1; }
            else   { mbar_wait_cta(bar0_loc, ph0); ph0 ^= 1; }
        }
        __syncthreads();                          // S1: peer half + own half visible

        float cmax  = cbuf[p][0];
        float cpass = (tid < 128) ? cbuf[p][qbase + tid] : 0.0f;
        if (tid < SS) se[tid] = __expf(cbuf[p][tid] - cmax);
        __syncthreads();                          // S2: se visible

        // 16 se values for this warp's n-range (broadcast LDS.128 x4)
        const float4* sv4 = (const float4*)&se[wid << 4];
        float a0 = 0.f, a1 = 0.f, a2 = 0.f, a3 = 0.f;
#pragma unroll
        for (int g = 0; g < 4; ++g) {
            float4 sv = sv4[g];
#pragma unroll
            for (int k = 0; k < 4; ++k) {
                uint2 v = PF[g * 4 + k];
                float sej = (k == 0) ? sv.x : (k == 1) ? sv.y : (k == 2) ? sv.z : sv.w;
                a0 = fmaf(__uint_as_float(v.x << 16),          sej, a0);
                a1 = fmaf(__uint_as_float(v.x & 0xFFFF0000u),  sej, a1);
                a2 = fmaf(__uint_as_float(v.y << 16),          sej, a2);
                a3 = fmaf(__uint_as_float(v.y & 0xFFFF0000u),  sej, a3);
            }
        }
        // prefetch next step's M and G while the reduction + exchange happen
        int xn = (s + 1 < LL) ? sx[LL - 2 - s] : 0;
        PFETCH(xn);
        gnext = (tid < 128) ? g_Gtab[xn * SS + qbase + tid] : 0.0f;

        *(float4*)&spart[(wid << 7) + (lane << 2)] = make_float4(a0, a1, a2, a3);
        __syncthreads();                          // S3: partials visible

        if (tid < 128) {
            float ssum = 0.f;
#pragma unroll
            for (int g = 0; g < 16; ++g) ssum += spart[(g << 7) + tid];
            float nc = (x != 0) ? (gcur + __logf(ssum) + cmax) : cpass;
            cbuf[np][qbase + tid] = nc;                         // own half, local
            asm volatile("st.async.shared::cluster.mbarrier::complete_tx::bytes.f32 "
                         "[%0], %1, [%2];"
                         :: "r"(np ? ch_rem1 : ch_rem0), "f"(nc),
                            "r"(np ? bar_rem1 : bar_rem0) : "memory");
        }
        gcur = gnext;
        // next iteration's S1 orders the local STS; the barrier orders the peer data
    }

    // step 511 wrote into cbuf[0] / bars[0]
    mbar_wait_cta(bar0_loc, ph0);
    __syncthreads();

    if (rank == 0 && wid == 0) {
        float vv[8];
        float m = -3.0e38f;
#pragma unroll
        for (int i = 0; i < 8; i++) {
            vv[i] = g_LAl[lane + 32 * i] + cbuf[0][lane + 32 * i];
            m = fmaxf(m, vv[i]);
        }
        m = wredMax(m);
        float sacc = 0.0f;
#pragma unroll
        for (int i = 0; i < 8; i++) sacc += __expf(vv[i] - m);
        sacc = wredSum(sacc);
        if (lane == 0) g_perseq[b] = __logf(sacc) + m;
    }
    cluster_sync_();   // no CTA exits while peer st.async may target it
#undef PFETCH
}

// -------- K6: out = sum_b per_seq[b] --------
__global__ void k_final(float* __restrict__ out) {
    float v = (threadIdx.x < BB) ? g_perseq[threadIdx.x] : 0.0f;
    v = wredSum(v);
    if (threadIdx.x == 0) out[0] = v;
}

// ============================================================================
extern "C" void kernel_launch(void* const* d_in, const int* in_sizes, int n_in,
                              void* d_out, int out_size) {
    const int*   xs    = (const int*)d_in[0];
    const float* alpha = (const float*)d_in[1];
    const float* omega = (const float*)d_in[2];
    const float* E     = (const float*)d_in[3];
    const float* T     = (const float*)d_in[4];
    float* out = (float*)d_out;

    k_rowconst_T<<<(SS * SS) / 8, 256>>>(T);
    k_small<<<33, 256>>>(E, alpha, omega);
    k_gtab<<<SS, 256>>>(E);
    k_buildM<<<dim3(8, 8, SS), dim3(32, 8)>>>(T);
    k_forward<<<BB * 2, NT>>>(xs);        // 16 clusters x 2 CTAs x 512 threads
    k_final<<<1, 32>>>(out);
}

// round 10
// speedup vs baseline: 2.3428x; 1.0678x over previous
#include <cuda_runtime.h>
#include <cuda_bf16.h>
#include <cstdint>

// ============================================================================
// S = 256 states/vocab, B = 16 sequences, L = 512 tokens.
// sparsemax_loss_vec(z)[y] = C(z) - z[y], C(z) = tau + 0.5*sum(p^2) + 0.5
// Backward recurrence (log semiring):
//   c_t[q] = G[x][q] + log( sum_n exp(-T[q,x,n]) * exp(c_{t+1}[n] - cmax) ) + cmax
//   G[x][q] = cE[q] - E[q,x] + cT[q,x]
// out = sum_b LSE_q( (cA - alpha[q]) + c_0[b,q] ),  c_L[q] = cOmega - omega[q]
//
// k_forward R10: one batch per 2-CTA cluster (512 thr/CTA). cmax is CTA-local
// (own chart value -> exact math, no peer dependency), so warps covering the
// CTA's OWN n-half compute immediately after syncthreads while only the 8
// peer-half warps wait on the mbarrier: the pairwise DSMEM flight hides under
// the own-half warps' FMA issue. M stored paired-n: u32 = bf16(n),bf16(n+1)
// at same q -> 8x LDG.128 prefetch per thread (half the LSU issue of R9).
// ============================================================================

#define SS 256
#define BB 16
#define LL 512
#define NT 512

// -------- device scratch --------
__device__ float    g_cT[SS * SS];
__device__ float    g_cE[SS];
__device__ float    g_Gtab[SS * SS];          // [x][q]
__device__ float    g_c0[SS];
__device__ float    g_LAl[SS];
__device__ unsigned g_M2[(size_t)SS * SS * SS / 2];  // [x][n/2][q]: u32 = bf16(n even)|bf16(n odd)<<16
__device__ float    g_perseq[BB];

// -------- helpers --------
__device__ __forceinline__ float wredMax(float v) {
#pragma unroll
    for (int o = 16; o; o >>= 1) v = fmaxf(v, __shfl_xor_sync(0xffffffffu, v, o));
    return v;
}
__device__ __forceinline__ float wredSum(float v) {
#pragma unroll
    for (int o = 16; o; o >>= 1) v += __shfl_xor_sync(0xffffffffu, v, o);
    return v;
}

// MUFU-free exp (|x| <= ~0.8 here)
__device__ __forceinline__ float exp_poly(float x) {
    float y = x * 1.44269504088896341f;
    float n = rintf(y);
    float t = (y - n) * 0.6931471805599453f;
    float p = 1.98412698412698413e-4f;
    p = fmaf(p, t, 1.38888888888888889e-3f);
    p = fmaf(p, t, 8.33333333333333333e-3f);
    p = fmaf(p, t, 4.16666666666666667e-2f);
    p = fmaf(p, t, 1.66666666666666667e-1f);
    p = fmaf(p, t, 0.5f);
    p = fmaf(p, t, 1.0f);
    p = fmaf(p, t, 1.0f);
    return p * __int_as_float(((int)n + 127) << 23);
}

// C(z) via Newton on f(tau) = sum relu(z - tau) - 1 (bit-identical output vs
// bisection across R6-R9; C stationary in tau at the optimum).
__device__ __forceinline__ float sparse_c8(const float v[8]) {
    float zmax = v[0];
#pragma unroll
    for (int i = 1; i < 8; i++) zmax = fmaxf(zmax, v[i]);
    zmax = wredMax(zmax);
    float tau = zmax - 1.0f;
#pragma unroll 1
    for (int it = 0; it < 24; ++it) {
        float sl = 0.0f, kl = 0.0f;
#pragma unroll
        for (int i = 0; i < 8; i++) {
            float d = v[i] - tau;
            if (d > 0.0f) { sl += d; kl += 1.0f; }
        }
#pragma unroll
        for (int o = 16; o; o >>= 1) {
            sl += __shfl_xor_sync(0xffffffffu, sl, o);
            kl += __shfl_xor_sync(0xffffffffu, kl, o);
        }
        float f = sl - 1.0f;
        if (f <= 1e-6f) break;            // warp-uniform
        tau += __fdividef(f, kl);
    }
    float s2 = 0.0f;
#pragma unroll
    for (int i = 0; i < 8; i++) {
        float p = fmaxf(v[i] - tau, 0.0f);
        s2 = fmaf(p, p, s2);
    }
    s2 = wredSum(s2);
    return tau + 0.5f * s2 + 0.5f;
}

__device__ __forceinline__ void load_row8(const float* __restrict__ z, int lane, float v[8]) {
    const float4* z4 = reinterpret_cast<const float4*>(z);
    float4 a = z4[lane];
    float4 b = z4[lane + 32];
    v[0] = a.x; v[1] = a.y; v[2] = a.z; v[3] = a.w;
    v[4] = b.x; v[5] = b.y; v[6] = b.z; v[7] = b.w;
}

// -------- K1: per-row C for all 65536 rows of T --------
__global__ void __launch_bounds__(256) k_rowconst_T(const float* __restrict__ T) {
    int warp = (blockIdx.x * blockDim.x + threadIdx.x) >> 5;
    int lane = threadIdx.x & 31;
    float v[8];
    load_row8(T + (size_t)warp * SS, lane, v);
    float c = sparse_c8(v);
    if (lane == 0) g_cT[warp] = c;
}

// -------- K2: C for E rows, alpha, omega --------
__global__ void __launch_bounds__(256) k_small(const float* __restrict__ E,
                                               const float* __restrict__ al,
                                               const float* __restrict__ om) {
    int warp = (blockIdx.x * blockDim.x + threadIdx.x) >> 5;
    int lane = threadIdx.x & 31;
    float v[8];
    if (warp < SS) {
        load_row8(E + (size_t)warp * SS, lane, v);
        float c = sparse_c8(v);
        if (lane == 0) g_cE[warp] = c;
    } else if (warp == SS) {
        load_row8(al, lane, v);
        float c = sparse_c8(v);
#pragma unroll
        for (int i = 0; i < 8; i++) g_LAl[lane + 32 * i] = c - al[lane + 32 * i];
    } else if (warp == SS + 1) {
        load_row8(om, lane, v);
        float c = sparse_c8(v);
#pragma unroll
        for (int i = 0; i < 8; i++) g_c0[lane + 32 * i] = c - om[lane + 32 * i];
    }
}

// -------- K3: G[x][q] --------
__global__ void __launch_bounds__(256) k_gtab(const float* __restrict__ E) {
    int x = blockIdx.x, q = threadIdx.x;
    g_Gtab[x * SS + q] = g_cE[q] - E[q * SS + x] + g_cT[q * SS + x];
}

// -------- K4: M2[x][n/2][q] = pack(bf16(exp(-T[q,x,n])), bf16(exp(-T[q,x,n+1]))) --------
__global__ void __launch_bounds__(256) k_buildM(const float* __restrict__ T) {
    __shared__ float tile[32][33];
    int x  = blockIdx.z;
    int q0 = blockIdx.x << 5, n0 = blockIdx.y << 5;
    int tx = threadIdx.x, ty = threadIdx.y;
#pragma unroll
    for (int i = 0; i < 32; i += 8) {
        int q = q0 + ty + i;
        tile[ty + i][tx] = T[(unsigned)q * 65536u + (unsigned)x * 256u + n0 + tx];
    }
    __syncthreads();
    // tile[q_local][n_local]; write u32 npair words, fully coalesced over q=tx
#pragma unroll
    for (int i = 0; i < 16; i += 8) {
        int npl = ty + i;                      // 0..15 local npair
        float v0 = exp_poly(-tile[tx][2 * npl]);
        float v1 = exp_poly(-tile[tx][2 * npl + 1]);
        __nv_bfloat162 h2 = __floats2bfloat162_rn(v0, v1);   // low = v0 (n even)
        g_M2[((size_t)x << 15) + (size_t)(((n0 >> 1) + npl) << 8) + (q0 + tx)]
            = *reinterpret_cast<unsigned*>(&h2);
    }
}

// -------- cluster primitives --------
__device__ __forceinline__ unsigned smem_u32(const void* p) {
    return (unsigned)__cvta_generic_to_shared(p);
}
__device__ __forceinline__ unsigned mapa_u32(unsigned local_smem, unsigned target_rank) {
    unsigned remote;
    asm volatile("mapa.shared::cluster.u32 %0, %1, %2;"
                 : "=r"(remote) : "r"(local_smem), "r"(target_rank));
    return remote;
}
__device__ __forceinline__ void cluster_sync_() {
    asm volatile("barrier.cluster.arrive.aligned;" ::: "memory");
    asm volatile("barrier.cluster.wait.aligned;"   ::: "memory");
}
__device__ __forceinline__ void mbar_wait_cta(unsigned addr, unsigned parity) {
    asm volatile(
        "{\n\t.reg .pred P;\n\t"
        "WAITLOOP_%=:\n\t"
        "mbarrier.try_wait.parity.acquire.cta.shared::cta.b64 P, [%0], %1, 0x989680;\n\t"
        "@P bra.uni WAITDONE_%=;\n\t"
        "bra.uni WAITLOOP_%=;\n\t"
        "WAITDONE_%=:\n\t}"
        :: "r"(addr), "r"(parity) : "memory");
}

// -------- K5: backward recursion, one batch per 2-CTA cluster --------------
// CTA rank r owns q,n in [128r, 128r+128). Warp w covers n in [16w, 16w+16)
// (npairs 8w..8w+7); lane covers 4 consecutive q. Warps whose n-range is the
// CTA's own half never wait; peer-half warps wait on the pairwise mbarrier.
__global__ void __cluster_dims__(2, 1, 1) __launch_bounds__(NT, 1)
k_forward(const int* __restrict__ xs) {
    __shared__ float cbuf[2][SS];                       // full chart, dbl buffered
    __shared__ __align__(16) float sew[16][16];         // per-warp se slice
    __shared__ __align__(16) float spart[16 * 128];     // 16 n-groups x 128 q
    __shared__ int   sx[LL];
    __shared__ __align__(8) unsigned long long bars[2];

    const int tid  = threadIdx.x;
    const int lane = tid & 31, wid = tid >> 5;
    const unsigned rank = (unsigned)(blockIdx.x & 1);
    const unsigned peer = rank ^ 1u;
    const int b  = blockIdx.x >> 1;
    const int qbase = (int)rank * 128;
    const bool ownw = ((wid < 8) == (rank == 0));       // warp's n-half is local

    if (tid < LL) sx[tid] = xs[b * LL + tid];
    if (tid < SS) cbuf[0][tid] = g_c0[tid];
    if (tid == 0) {
        asm volatile("mbarrier.init.shared.b64 [%0], %1;"
                     :: "r"(smem_u32(&bars[0])), "r"(1) : "memory");
        asm volatile("mbarrier.init.shared.b64 [%0], %1;"
                     :: "r"(smem_u32(&bars[1])), "r"(1) : "memory");
    }
    __syncthreads();
    cluster_sync_();   // inits visible before any st.async

    const unsigned bar0_loc = smem_u32(&bars[0]);
    const unsigned bar1_loc = smem_u32(&bars[1]);
    const unsigned bar_rem0 = mapa_u32(bar0_loc, peer);
    const unsigned bar_rem1 = mapa_u32(bar1_loc, peer);
    const unsigned ch_rem0  = mapa_u32(smem_u32(&cbuf[0][qbase + tid]), peer);
    const unsigned ch_rem1  = mapa_u32(smem_u32(&cbuf[1][qbase + tid]), peer);

    uint4 PF[8];                         // 8 npairs x (4 q x 2 n) bf16 = 32 regs

#define PFETCH(xv) do {                                                           \
    const uint4* _mp = (const uint4*)g_M2 + (((size_t)(unsigned)(xv)) << 13)      \
                         + ((unsigned)(wid << 6)) + (unsigned)((qbase >> 2) + lane);\
    _Pragma("unroll")                                                             \
    for (int _j = 0; _j < 8; _j++) PF[_j] = __ldg(_mp + (_j << 6));               \
} while (0)

    float gcur = (tid < 128) ? g_Gtab[sx[LL - 1] * SS + qbase + tid] : 0.0f;
    PFETCH(sx[LL - 1]);

    unsigned ph0 = 0, ph1 = 0;
#pragma unroll 1
    for (int s = 0; s < LL; ++s) {
        const int p = s & 1, np = p ^ 1;
        const int x = sx[LL - 1 - s];

        // arm receive barrier for NEXT-step incoming peer half (128 x 4B).
        // Ordered after bars[np]'s previous phase completion via last step's
        // pre-reduce __syncthreads (the peer-half warps' wait).
        if (tid == 0)
            asm volatile("mbarrier.arrive.expect_tx.shared.b64 _, [%0], %1;"
                         :: "r"(np ? bar1_loc : bar0_loc), "r"(512) : "memory");
        __syncthreads();                       // S1: local chart writes visible

        if (s) {
            unsigned& ph = p ? ph1 : ph0;
            if (!ownw) mbar_wait_cta(p ? bar1_loc : bar0_loc, ph);
            ph ^= 1;                           // all threads track parity
        }

        // CTA-local shift (own-half value: exact math, any uniform shift ok)
        float cmaxl = cbuf[p][qbase];
        // per-warp se over this warp's 16 n values (own warps: local data;
        // peer warps: ordered by the mbarrier acquire above)
        if (lane < 16)
            sew[wid][lane] = __expf(cbuf[p][(wid << 4) + lane] - cmaxl);
        __syncwarp();

        float a0 = 0.f, a1 = 0.f, a2 = 0.f, a3 = 0.f;
        const float4* sv4 = (const float4*)sew[wid];
#pragma unroll
        for (int g = 0; g < 4; ++g) {
            float4 sv = sv4[g];
            {
                uint4 v = PF[2 * g];           // npair 2g: se = (sv.x, sv.y)
                a0 = fmaf(__uint_as_float(v.x << 16), sv.x, a0);
                a0 = fmaf(__uint_as_float(v.x & 0xFFFF0000u), sv.y, a0);
                a1 = fmaf(__uint_as_float(v.y << 16), sv.x, a1);
                a1 = fmaf(__uint_as_float(v.y & 0xFFFF0000u), sv.y, a1);
                a2 = fmaf(__uint_as_float(v.z << 16), sv.x, a2);
                a2 = fmaf(__uint_as_float(v.z & 0xFFFF0000u), sv.y, a2);
                a3 = fmaf(__uint_as_float(v.w << 16), sv.x, a3);
                a3 = fmaf(__uint_as_float(v.w & 0xFFFF0000u), sv.y, a3);
            }
            {
                uint4 v = PF[2 * g + 1];       // npair 2g+1: se = (sv.z, sv.w)
                a0 = fmaf(__uint_as_float(v.x << 16), sv.z, a0);
                a0 = fmaf(__uint_as_float(v.x & 0xFFFF0000u), sv.w, a0);
                a1 = fmaf(__uint_as_float(v.y << 16), sv.z, a1);
                a1 = fmaf(__uint_as_float(v.y & 0xFFFF0000u), sv.w, a1);
                a2 = fmaf(__uint_as_float(v.z << 16), sv.z, a2);
                a2 = fmaf(__uint_as_float(v.z & 0xFFFF0000u), sv.w, a2);
                a3 = fmaf(__uint_as_float(v.w << 16), sv.z, a3);
                a3 = fmaf(__uint_as_float(v.w & 0xFFFF0000u), sv.w, a3);
            }
        }
        *(float4*)&spart[(wid << 7) + (lane << 2)] = make_float4(a0, a1, a2, a3);

        // prefetch next step's M and G while partials settle / peer lags
        int xn = (s + 1 < LL) ? sx[LL - 2 - s] : 0;
        PFETCH(xn);
        float gnext = (tid < 128) ? g_Gtab[xn * SS + qbase + tid] : 0.0f;

        __syncthreads();                       // S3: partials visible

        if (tid < 128) {
            float ssum = 0.f;
#pragma unroll
            for (int g = 0; g < 16; ++g) ssum += spart[(g << 7) + tid];
            float nc = (x != 0) ? (gcur + __logf(ssum) + cmaxl)
                                : cbuf[p][qbase + tid];       // padding passthrough
            cbuf[np][qbase + tid] = nc;                       // own half, local
            asm volatile("st.async.shared::cluster.mbarrier::complete_tx::bytes.f32 "
                         "[%0], %1, [%2];"
                         :: "r"(np ? ch_rem1 : ch_rem0), "f"(nc),
                            "r"(np ? bar_rem1 : bar_rem0) : "memory");
        }
        gcur = gnext;
    }

    // step 511 wrote into cbuf[0] / bars[0] (phase parity = ph0)
    mbar_wait_cta(bar0_loc, ph0);
    __syncthreads();

    if (rank == 0 && wid == 0) {
        float vv[8];
        float m = -3.0e38f;
#pragma unroll
        for (int i = 0; i < 8; i++) {
            vv[i] = g_LAl[lane + 32 * i] + cbuf[0][lane + 32 * i];
            m = fmaxf(m, vv[i]);
        }
        m = wredMax(m);
        float sacc = 0.0f;
#pragma unroll
        for (int i = 0; i < 8; i++) sacc += __expf(vv[i] - m);
        sacc = wredSum(sacc);
        if (lane == 0) g_perseq[b] = __logf(sacc) + m;
    }
    cluster_sync_();   // no CTA exits while peer st.async may target it
#undef PFETCH
}

// -------- K6: out = sum_b per_seq[b] --------
__global__ void k_final(float* __restrict__ out) {
    float v = (threadIdx.x < BB) ? g_perseq[threadIdx.x] : 0.0f;
    v = wredSum(v);
    if (threadIdx.x == 0) out[0] = v;
}

// ============================================================================
extern "C" void kernel_launch(void* const* d_in, const int* in_sizes, int n_in,
                              void* d_out, int out_size) {
    const int*   xs    = (const int*)d_in[0];
    const float* alpha = (const float*)d_in[1];
    const float* omega = (const float*)d_in[2];
    const float* E     = (const float*)d_in[3];
    const float* T     = (const float*)d_in[4];
    float* out = (float*)d_out;

    k_rowconst_T<<<(SS * SS) / 8, 256>>>(T);
    k_small<<<33, 256>>>(E, alpha, omega);
    k_gtab<<<SS, 256>>>(E);
    k_buildM<<<dim3(8, 8, SS), dim3(32, 8)>>>(T);
    k_forward<<<BB * 2, NT>>>(xs);        // 16 clusters x 2 CTAs x 512 threads
    k_final<<<1, 32>>>(out);
}